// round 13
// baseline (speedup 1.0000x reference)
#include <cuda_runtime.h>
#include <cuda_fp16.h>
#include <cstdint>

// Problem: B=4,S=4096 -> T=16384 tokens; IN_F=OUT_F=4096; G=32; GS=GO=128.
// y[t, g*128+n] = sum_k x[t, perm[g*128+k]] * W[g,n,k] + b[g,n]
// Numerics: x -> fp16, W -> fp16 hi + lo; y = xh*Wh + xh*Wl, f32 accum.
#define IN_F   4096
#define G      32
#define TMAX   16384
#define TILE_T 128
#define CHUNK  8            // token tiles per GEMM CTA

// ---------------- device scratch (static; no allocation) ----------------
__device__ int      g_perm[IN_F];
__device__ uint32_t g_whf[64 * 4096];     // W hi fragments per half-group (fp16x2)
__device__ uint32_t g_wlf[64 * 4096];     // W lo fragments (fp16x2)
// Pre-swizzled fp16 A tiles: [ttile=128][g=32][32KB tile]
__device__ unsigned char g_xt[(size_t)128 * 32 * 32768];

__device__ __forceinline__ uint32_t smem_u32(const void* p) {
    uint32_t a;
    asm("{ .reg .u64 t; cvta.to.shared.u64 t, %1; cvt.u32.u64 %0, t; }" : "=r"(a) : "l"(p));
    return a;
}

__device__ __forceinline__ uint32_t pack_h2(float lo, float hi) {
    __half2 h = __floats2half2_rn(lo, hi);   // lo -> low 16 bits
    return *(uint32_t*)&h;
}

// ---------------- pass 0a: normalize perm (int64-or-int32 -> int32) ----------------
__global__ void convert_perm_kernel(const int* __restrict__ p32) {
    __shared__ int is64;
    if (threadIdx.x == 0) {
        int all0 = 1;
        #pragma unroll
        for (int i = 1; i < 16; i += 2) all0 &= (p32[i] == 0);
        is64 = all0;
    }
    __syncthreads();
    const int w = is64;
    for (int i = threadIdx.x; i < IN_F; i += blockDim.x)
        g_perm[i] = w ? p32[2 * i] : p32[i];
}

// ---------------- pass 0b: W -> fp16 hi/lo, gmem-LDG fragment order ----------------
// e = (((wn*8 + ks)*32 + lane)*4 + nt)*2 + r
//   n  = (hg&1)*64 + wn*32 + nt*8 + lane/4 ; k0 = ks*16 + 2*(lane&3) + r*8
__global__ void wprep_kernel(const float* __restrict__ W) {
    const int hg = blockIdx.x;            // 0..63
    const int g = hg >> 1;
    for (int e = threadIdx.x; e < 4096; e += blockDim.x) {
        const int r    = e & 1;
        const int nt   = (e >> 1) & 3;
        const int lane = (e >> 3) & 31;
        const int ks   = (e >> 8) & 7;
        const int wn   = e >> 11;
        const int n    = (hg & 1) * 64 + wn * 32 + nt * 8 + (lane >> 2);
        const int k0   = ks * 16 + 2 * (lane & 3) + r * 8;
        const float v0 = W[((size_t)g * 128 + n) * 128 + k0];
        const float v1 = W[((size_t)g * 128 + n) * 128 + k0 + 1];
        const float h0 = __half2float(__float2half_rn(v0));
        const float h1 = __half2float(__float2half_rn(v1));
        g_whf[hg * 4096 + e] = pack_h2(h0, h1);
        g_wlf[hg * 4096 + e] = pack_h2(v0 - h0, v1 - h1);
    }
}

// ---------------- pass 1: permute + fp16 convert into GEMM-ready tiles ----------------
// Block: 8 tokens, 256 threads, 64 KB smem fp16 rows. (Unchanged from R11.)
__global__ __launch_bounds__(256) void xprep_kernel(const float* __restrict__ x) {
    extern __shared__ unsigned short rows16[];      // 8 * 4096 fp16 = 64 KB
    const int t0    = blockIdx.x * 8;
    const int ttile = t0 >> 7;
    const int tbase = t0 & 127;
    const int tid = threadIdx.x, lane = tid & 31, wid = tid >> 5;

    {
        const float4* src = (const float4*)(x + (size_t)t0 * IN_F);
        uint2* r2 = (uint2*)rows16;
        #pragma unroll 8
        for (int i = tid; i < 8192; i += 256) {
            const float4 v = src[i];
            r2[i] = make_uint2(pack_h2(v.x, v.y), pack_h2(v.z, v.w));
        }
    }
    __syncthreads();

    const int q       = lane & 15;                  // 16B chunk within row
    const int half_id = wid * 2 + (lane >> 4);      // 0..15

    #pragma unroll 4
    for (int it = 0; it < 16; ++it) {
        const int rt  = it * 16 + half_id;          // 0..255
        const int tok = rt >> 5;                    // 0..7
        const int g   = rt & 31;
        const unsigned short* row = rows16 + tok * IN_F;

        const int4* pp = (const int4*)(g_perm + g * 128 + 8 * q);
        const int4 pa = pp[0];
        const int4 pb = pp[1];

        uint4 v;
        v.x = (uint32_t)row[pa.x] | ((uint32_t)row[pa.y] << 16);
        v.y = (uint32_t)row[pa.z] | ((uint32_t)row[pa.w] << 16);
        v.z = (uint32_t)row[pb.x] | ((uint32_t)row[pb.y] << 16);
        v.w = (uint32_t)row[pb.z] | ((uint32_t)row[pb.w] << 16);

        const uint32_t t   = (uint32_t)(tbase + tok);
        const uint32_t off = t * 256 + (((uint32_t)q ^ (t & 7)) << 4);
        *(uint4*)(g_xt + ((size_t)ttile * 32 + g) * 32768 + off) = v;
    }
}

// ---------------- pass 2: HMMA GEMM, persistent-chunk + double-buffered A ----------
// CTA: one half-group x CHUNK token tiles. 128 threads, warp grid 2(m) x 2(n),
// warp tile 64x32. smem = two 32KB A buffers; A(i+1) cp.async overlaps compute
// of A(i). B (hi/lo) via LDG, L1-hot across the whole chunk.
#define SM_SZ 65536

__global__ __launch_bounds__(128)
void bdl_mma_kernel(const float* __restrict__ bias, float* __restrict__ out)
{
    extern __shared__ char smem[];
    const uint32_t sb = smem_u32(smem);
    const int hg = blockIdx.x;            // 0..63
    const int g  = hg >> 1;
    const int tt0 = blockIdx.y * CHUNK;   // first token tile of this chunk
    const int tid = threadIdx.x, lane = tid & 31, wid = tid >> 5;
    const int wm = wid & 1;
    const int wn = wid >> 1;

    const uint4* bhp = (const uint4*)(g_whf + hg * 4096 + wn * 2048);
    const uint4* blp = (const uint4*)(g_wlf + hg * 4096 + wn * 2048);

    // bias for this warp's 32 columns, hoisted out of the tile loop
    const int colbase = g * 128 + (hg & 1) * 64 + wn * 32;
    float bb0[4], bb1[4];
    #pragma unroll
    for (int nt = 0; nt < 4; ++nt) {
        const int col = colbase + nt * 8 + 2 * (lane & 3);
        bb0[nt] = bias[col];
        bb1[nt] = bias[col + 1];
    }

    // prologue: issue A(tile 0) into buffer 0
    {
        const unsigned char* sa = g_xt + ((size_t)tt0 * 32 + g) * 32768;
        #pragma unroll 4
        for (int e = tid; e < 2048; e += 128)
            asm volatile("cp.async.cg.shared.global [%0], [%1], 16;"
                         :: "r"(sb + e * 16), "l"(sa + e * 16));
        asm volatile("cp.async.commit_group;");
    }

    for (int it = 0; it < CHUNK; ++it) {
        // issue A(it+1) into the other buffer (its last reader finished at
        // the tail __syncthreads of iteration it-1)
        if (it + 1 < CHUNK) {
            const unsigned char* sa =
                g_xt + ((size_t)(tt0 + it + 1) * 32 + g) * 32768;
            const uint32_t dst = sb + ((it + 1) & 1) * 32768;
            #pragma unroll 4
            for (int e = tid; e < 2048; e += 128)
                asm volatile("cp.async.cg.shared.global [%0], [%1], 16;"
                             :: "r"(dst + e * 16), "l"(sa + e * 16));
            asm volatile("cp.async.commit_group;");
            asm volatile("cp.async.wait_group 1;");   // A(it) done, A(it+1) in flight
        } else {
            asm volatile("cp.async.wait_group 0;");   // last tile: drain
        }
        __syncthreads();

        const uint32_t abase = sb + (it & 1) * 32768;

        float acc[4][4][4];
        #pragma unroll
        for (int mt = 0; mt < 4; ++mt)
            #pragma unroll
            for (int nt = 0; nt < 4; ++nt)
                #pragma unroll
                for (int q = 0; q < 4; ++q) acc[mt][nt][q] = 0.0f;

        #pragma unroll
        for (int ks = 0; ks < 8; ++ks) {
            const int bidx = (ks * 32 + lane) * 2;
            const uint4 h01 = __ldg(&bhp[bidx]);
            const uint4 h23 = __ldg(&bhp[bidx + 1]);
            const uint4 l01 = __ldg(&blp[bidx]);
            const uint4 l23 = __ldg(&blp[bidx + 1]);
            const uint32_t bh[4][2] = {{h01.x,h01.y},{h01.z,h01.w},{h23.x,h23.y},{h23.z,h23.w}};
            const uint32_t bl[4][2] = {{l01.x,l01.y},{l01.z,l01.w},{l23.x,l23.y},{l23.z,l23.w}};

            uint32_t ah[4][4];
            #pragma unroll
            for (int mt = 0; mt < 4; ++mt) {
                const uint32_t row = (uint32_t)(wm * 64 + mt * 16 + (lane & 15));
                const uint32_t c   = (uint32_t)(2 * ks + (lane >> 4));
                const uint32_t aoff = row * 256 + ((c ^ (row & 7)) << 4);
                asm volatile("ldmatrix.sync.aligned.m8n8.x4.shared.b16 {%0,%1,%2,%3}, [%4];"
                             : "=r"(ah[mt][0]), "=r"(ah[mt][1]), "=r"(ah[mt][2]), "=r"(ah[mt][3])
                             : "r"(abase + aoff));
            }
            #pragma unroll
            for (int mt = 0; mt < 4; ++mt)
                #pragma unroll
                for (int nt = 0; nt < 4; ++nt) {
                    asm volatile(
                        "mma.sync.aligned.m16n8k16.row.col.f32.f16.f16.f32 "
                        "{%0,%1,%2,%3}, {%4,%5,%6,%7}, {%8,%9}, {%0,%1,%2,%3};"
                        : "+f"(acc[mt][nt][0]), "+f"(acc[mt][nt][1]),
                          "+f"(acc[mt][nt][2]), "+f"(acc[mt][nt][3])
                        : "r"(ah[mt][0]), "r"(ah[mt][1]), "r"(ah[mt][2]), "r"(ah[mt][3]),
                          "r"(bh[nt][0]), "r"(bh[nt][1]));
                    asm volatile(
                        "mma.sync.aligned.m16n8k16.row.col.f32.f16.f16.f32 "
                        "{%0,%1,%2,%3}, {%4,%5,%6,%7}, {%8,%9}, {%0,%1,%2,%3};"
                        : "+f"(acc[mt][nt][0]), "+f"(acc[mt][nt][1]),
                          "+f"(acc[mt][nt][2]), "+f"(acc[mt][nt][3])
                        : "r"(ah[mt][0]), "r"(ah[mt][1]), "r"(ah[mt][2]), "r"(ah[mt][3]),
                          "r"(bl[nt][0]), "r"(bl[nt][1]));
                }
        }

        // epilogue: bias + st.v2 (c-fragment layout)
        const int t0 = (tt0 + it) * TILE_T;
        #pragma unroll
        for (int nt = 0; nt < 4; ++nt) {
            const int col = colbase + nt * 8 + 2 * (lane & 3);
            #pragma unroll
            for (int mt = 0; mt < 4; ++mt) {
                const int r0 = t0 + wm * 64 + mt * 16 + (lane >> 2);
                float2 v0 = make_float2(acc[mt][nt][0] + bb0[nt], acc[mt][nt][1] + bb1[nt]);
                float2 v1 = make_float2(acc[mt][nt][2] + bb0[nt], acc[mt][nt][3] + bb1[nt]);
                *(float2*)(out + (size_t)r0 * IN_F + col)       = v0;
                *(float2*)(out + (size_t)(r0 + 8) * IN_F + col) = v1;
            }
        }
        __syncthreads();   // protect buffer (it+1)&1 before next-iter issue
    }
}

// ---------------- launch ----------------
extern "C" void kernel_launch(void* const* d_in, const int* in_sizes, int n_in,
                              void* d_out, int out_size)
{
    const float* x    = (const float*)d_in[0];
    const int*   perm = (const int*)d_in[1];
    const float* W    = (const float*)d_in[2];
    const float* bias = (const float*)d_in[3];
    float* out = (float*)d_out;

    const int T = in_sizes[0] / IN_F;   // 16384

    convert_perm_kernel<<<1, 1024>>>(perm);
    wprep_kernel<<<64, 256>>>(W);

    cudaFuncSetAttribute(xprep_kernel,
                         cudaFuncAttributeMaxDynamicSharedMemorySize, 65536);
    xprep_kernel<<<T / 8, 256, 65536>>>(x);

    cudaFuncSetAttribute(bdl_mma_kernel,
                         cudaFuncAttributeMaxDynamicSharedMemorySize, SM_SZ);
    dim3 grid(64, T / (TILE_T * CHUNK));   // (64 hg, 16 chunks)
    bdl_mma_kernel<<<grid, 128, SM_SZ>>>(bias, out);
}

// round 14
// speedup vs baseline: 1.1455x; 1.1455x over previous
#include <cuda_runtime.h>
#include <cuda_fp16.h>
#include <cstdint>

// Problem: B=4,S=4096 -> T=16384 tokens; IN_F=OUT_F=4096; G=32; GS=GO=128.
// y[t, g*128+n] = sum_k x[t, perm[g*128+k]] * W[g,n,k] + b[g,n]
// Numerics: x -> fp16, W -> fp16 hi + lo; y = xh*Wh + xh*Wl, f32 accum.
#define IN_F   4096
#define G      32
#define TMAX   16384
#define TILE_T 128

// ---------------- device scratch (static; no allocation) ----------------
__device__ int      g_perm[IN_F];
__device__ uint32_t g_whf[64 * 4096];     // W hi fragments per half-group (fp16x2)
__device__ uint32_t g_wlf[64 * 4096];     // W lo fragments (fp16x2)
// Pre-swizzled fp16 A tiles: [ttile=128][g=32][32KB tile]
__device__ unsigned char g_xt[(size_t)128 * 32 * 32768];

__device__ __forceinline__ uint32_t smem_u32(const void* p) {
    uint32_t a;
    asm("{ .reg .u64 t; cvta.to.shared.u64 t, %1; cvt.u32.u64 %0, t; }" : "=r"(a) : "l"(p));
    return a;
}

__device__ __forceinline__ uint32_t pack_h2(float lo, float hi) {
    __half2 h = __floats2half2_rn(lo, hi);   // lo -> low 16 bits
    return *(uint32_t*)&h;
}

// ---------------- pass 0a: normalize perm (int64-or-int32 -> int32) ----------------
__global__ void convert_perm_kernel(const int* __restrict__ p32) {
    __shared__ int is64;
    if (threadIdx.x == 0) {
        int all0 = 1;
        #pragma unroll
        for (int i = 1; i < 16; i += 2) all0 &= (p32[i] == 0);
        is64 = all0;
    }
    __syncthreads();
    const int w = is64;
    for (int i = threadIdx.x; i < IN_F; i += blockDim.x)
        g_perm[i] = w ? p32[2 * i] : p32[i];
}

// ---------------- pass 0b: W -> fp16 hi/lo, LDS.64-friendly fragment order --------
// u32 index e in half-group: e = ((((wn*8 + ks)*4 + nt)*32) + lane)*2 + r
//   n  = (hg&1)*64 + wn*32 + nt*8 + lane/4 ; k0 = ks*16 + 2*(lane&3) + r*8
// Per (wn,ks,nt): 64 consecutive u32 across lanes -> conflict-free ld.shared.v2.
__global__ void wprep_kernel(const float* __restrict__ W) {
    const int hg = blockIdx.x;            // 0..63
    const int g = hg >> 1;
    for (int e = threadIdx.x; e < 4096; e += blockDim.x) {
        const int r    = e & 1;
        const int lane = (e >> 1) & 31;
        const int nt   = (e >> 6) & 3;
        const int ks   = (e >> 8) & 7;
        const int wn   = e >> 11;
        const int n    = (hg & 1) * 64 + wn * 32 + nt * 8 + (lane >> 2);
        const int k0   = ks * 16 + 2 * (lane & 3) + r * 8;
        const float v0 = W[((size_t)g * 128 + n) * 128 + k0];
        const float v1 = W[((size_t)g * 128 + n) * 128 + k0 + 1];
        const float h0 = __half2float(__float2half_rn(v0));
        const float h1 = __half2float(__float2half_rn(v1));
        g_whf[hg * 4096 + e] = pack_h2(h0, h1);
        g_wlf[hg * 4096 + e] = pack_h2(v0 - h0, v1 - h1);
    }
}

// ---------------- pass 1: permute + fp16 convert into GEMM-ready tiles ----------------
// Block: 8 tokens, 256 threads, 64 KB smem fp16 rows. (Unchanged from R11.)
__global__ __launch_bounds__(256) void xprep_kernel(const float* __restrict__ x) {
    extern __shared__ unsigned short rows16[];      // 8 * 4096 fp16 = 64 KB
    const int t0    = blockIdx.x * 8;
    const int ttile = t0 >> 7;
    const int tbase = t0 & 127;
    const int tid = threadIdx.x, lane = tid & 31, wid = tid >> 5;

    {
        const float4* src = (const float4*)(x + (size_t)t0 * IN_F);
        uint2* r2 = (uint2*)rows16;
        #pragma unroll 8
        for (int i = tid; i < 8192; i += 256) {
            const float4 v = src[i];
            r2[i] = make_uint2(pack_h2(v.x, v.y), pack_h2(v.z, v.w));
        }
    }
    __syncthreads();

    const int q       = lane & 15;                  // 16B chunk within row
    const int half_id = wid * 2 + (lane >> 4);      // 0..15

    #pragma unroll 4
    for (int it = 0; it < 16; ++it) {
        const int rt  = it * 16 + half_id;          // 0..255
        const int tok = rt >> 5;                    // 0..7
        const int g   = rt & 31;
        const unsigned short* row = rows16 + tok * IN_F;

        const int4* pp = (const int4*)(g_perm + g * 128 + 8 * q);
        const int4 pa = pp[0];
        const int4 pb = pp[1];

        uint4 v;
        v.x = (uint32_t)row[pa.x] | ((uint32_t)row[pa.y] << 16);
        v.y = (uint32_t)row[pa.z] | ((uint32_t)row[pa.w] << 16);
        v.z = (uint32_t)row[pb.x] | ((uint32_t)row[pb.y] << 16);
        v.w = (uint32_t)row[pb.z] | ((uint32_t)row[pb.w] << 16);

        const uint32_t t   = (uint32_t)(tbase + tok);
        const uint32_t off = t * 256 + (((uint32_t)q ^ (t & 7)) << 4);
        *(uint4*)(g_xt + ((size_t)ttile * 32 + g) * 32768 + off) = v;
    }
}

// ---------------- pass 2: HMMA block-diagonal GEMM, all-smem mainloop ------------
// CTA: 128 tokens x 64 outputs (half-group), 128 threads, warp grid 2x2,
// warp tile 64x32. Prologue cp.asyncs A (32KB) + B hi/lo (32KB) into smem in
// one group; mainloop touches ONLY smem (ldmatrix + LDS.64) + HMMA.
// smem 64KB -> 3 CTA/SM; regs ~140 < 170 cap.
#define SM_A   0
#define SM_BH  32768
#define SM_BL  49152
#define SM_SZ  65536

__global__ __launch_bounds__(128, 3)
void bdl_mma_kernel(const float* __restrict__ bias, float* __restrict__ out)
{
    extern __shared__ char smem[];
    const uint32_t sb = smem_u32(smem);
    const int hg = blockIdx.x;
    const int g  = hg >> 1;
    const int t0 = blockIdx.y * TILE_T;
    const int tid = threadIdx.x, lane = tid & 31, wid = tid >> 5;

    // --- prologue: A tile + B hi/lo via cp.async, one wait ---
    {
        const unsigned char* sa = g_xt + ((size_t)blockIdx.y * 32 + g) * 32768;
        #pragma unroll 4
        for (int e = tid; e < 2048; e += 128)
            asm volatile("cp.async.cg.shared.global [%0], [%1], 16;"
                         :: "r"(sb + SM_A + e * 16), "l"(sa + e * 16));
        const unsigned char* bh = (const unsigned char*)(g_whf + hg * 4096);
        const unsigned char* bl = (const unsigned char*)(g_wlf + hg * 4096);
        #pragma unroll 4
        for (int e = tid; e < 1024; e += 128) {
            asm volatile("cp.async.cg.shared.global [%0], [%1], 16;"
                         :: "r"(sb + SM_BH + e * 16), "l"(bh + e * 16));
            asm volatile("cp.async.cg.shared.global [%0], [%1], 16;"
                         :: "r"(sb + SM_BL + e * 16), "l"(bl + e * 16));
        }
        asm volatile("cp.async.commit_group;");
        asm volatile("cp.async.wait_group 0;");
    }
    __syncthreads();

    // --- mainloop: warp grid 2(m) x 2(n); warp tile 64 tokens x 32 outputs ---
    const int wm = wid & 1;
    const int wn = wid >> 1;

    // B slice base for this warp (bytes): wn*2048 u32 = 8192 B
    const uint32_t bh_base = sb + SM_BH + (uint32_t)wn * 8192 + (uint32_t)lane * 8;
    const uint32_t bl_base = sb + SM_BL + (uint32_t)wn * 8192 + (uint32_t)lane * 8;

    float acc[4][4][4];
    #pragma unroll
    for (int mt = 0; mt < 4; ++mt)
        #pragma unroll
        for (int nt = 0; nt < 4; ++nt)
            #pragma unroll
            for (int q = 0; q < 4; ++q) acc[mt][nt][q] = 0.0f;

    #pragma unroll
    for (int ks = 0; ks < 8; ++ks) {
        // B fragments: conflict-free LDS.64 per (ks,nt) slice (256B apart)
        uint32_t bh[4][2], bl[4][2];
        #pragma unroll
        for (int nt = 0; nt < 4; ++nt) {
            const uint32_t soff = (uint32_t)(ks * 4 + nt) * 256;
            asm volatile("ld.shared.v2.b32 {%0,%1}, [%2];"
                         : "=r"(bh[nt][0]), "=r"(bh[nt][1]) : "r"(bh_base + soff));
            asm volatile("ld.shared.v2.b32 {%0,%1}, [%2];"
                         : "=r"(bl[nt][0]), "=r"(bl[nt][1]) : "r"(bl_base + soff));
        }

        uint32_t ah[4][4];
        #pragma unroll
        for (int mt = 0; mt < 4; ++mt) {
            const uint32_t row = (uint32_t)(wm * 64 + mt * 16 + (lane & 15));
            const uint32_t c   = (uint32_t)(2 * ks + (lane >> 4));
            const uint32_t aoff = row * 256 + ((c ^ (row & 7)) << 4);
            asm volatile("ldmatrix.sync.aligned.m8n8.x4.shared.b16 {%0,%1,%2,%3}, [%4];"
                         : "=r"(ah[mt][0]), "=r"(ah[mt][1]), "=r"(ah[mt][2]), "=r"(ah[mt][3])
                         : "r"(sb + SM_A + aoff));
        }
        #pragma unroll
        for (int mt = 0; mt < 4; ++mt)
            #pragma unroll
            for (int nt = 0; nt < 4; ++nt) {
                asm volatile(
                    "mma.sync.aligned.m16n8k16.row.col.f32.f16.f16.f32 "
                    "{%0,%1,%2,%3}, {%4,%5,%6,%7}, {%8,%9}, {%0,%1,%2,%3};"
                    : "+f"(acc[mt][nt][0]), "+f"(acc[mt][nt][1]),
                      "+f"(acc[mt][nt][2]), "+f"(acc[mt][nt][3])
                    : "r"(ah[mt][0]), "r"(ah[mt][1]), "r"(ah[mt][2]), "r"(ah[mt][3]),
                      "r"(bh[nt][0]), "r"(bh[nt][1]));
                asm volatile(
                    "mma.sync.aligned.m16n8k16.row.col.f32.f16.f16.f32 "
                    "{%0,%1,%2,%3}, {%4,%5,%6,%7}, {%8,%9}, {%0,%1,%2,%3};"
                    : "+f"(acc[mt][nt][0]), "+f"(acc[mt][nt][1]),
                      "+f"(acc[mt][nt][2]), "+f"(acc[mt][nt][3])
                    : "r"(ah[mt][0]), "r"(ah[mt][1]), "r"(ah[mt][2]), "r"(ah[mt][3]),
                      "r"(bl[nt][0]), "r"(bl[nt][1]));
            }
    }

    // --- epilogue: bias + st.v2 (c-fragment layout) ---
    const int colbase = g * 128 + (hg & 1) * 64 + wn * 32;
    #pragma unroll
    for (int nt = 0; nt < 4; ++nt) {
        const int col = colbase + nt * 8 + 2 * (lane & 3);
        const float b0 = bias[col], b1 = bias[col + 1];
        #pragma unroll
        for (int mt = 0; mt < 4; ++mt) {
            const int r0 = t0 + wm * 64 + mt * 16 + (lane >> 2);
            float2 v0 = make_float2(acc[mt][nt][0] + b0, acc[mt][nt][1] + b1);
            float2 v1 = make_float2(acc[mt][nt][2] + b0, acc[mt][nt][3] + b1);
            *(float2*)(out + (size_t)r0 * IN_F + col)       = v0;
            *(float2*)(out + (size_t)(r0 + 8) * IN_F + col) = v1;
        }
    }
}

// ---------------- launch ----------------
extern "C" void kernel_launch(void* const* d_in, const int* in_sizes, int n_in,
                              void* d_out, int out_size)
{
    const float* x    = (const float*)d_in[0];
    const int*   perm = (const int*)d_in[1];
    const float* W    = (const float*)d_in[2];
    const float* bias = (const float*)d_in[3];
    float* out = (float*)d_out;

    const int T = in_sizes[0] / IN_F;   // 16384

    convert_perm_kernel<<<1, 1024>>>(perm);
    wprep_kernel<<<64, 256>>>(W);

    cudaFuncSetAttribute(xprep_kernel,
                         cudaFuncAttributeMaxDynamicSharedMemorySize, 65536);
    xprep_kernel<<<T / 8, 256, 65536>>>(x);

    cudaFuncSetAttribute(bdl_mma_kernel,
                         cudaFuncAttributeMaxDynamicSharedMemorySize, SM_SZ);
    dim3 grid(64, T / TILE_T);          // (64 half-groups, 128 token tiles)
    bdl_mma_kernel<<<grid, 128, SM_SZ>>>(bias, out);
}